// round 8
// baseline (speedup 1.0000x reference)
#include <cuda_runtime.h>
#include <cuda_bf16.h>

// LJ constants: EPSILON=1, SIGMA=1, CUTOFF=5
// SHIFT = 4*((1/5)^12 - (1/5)^6)
// per-edge half energy: h = 0.5*(4*(sr12 - sr6) - SHIFT) = 2*(sr12 - sr6) - SHIFT/2
static constexpr double SHIFT_D = 4.0 * (1.0 / 244140625.0 - 1.0 / 15625.0);
static constexpr float NEG_HALF_SHIFT = (float)(-0.5 * SHIFT_D);

__global__ void zero_out_kernel(float* __restrict__ out, int n) {
    int i = blockIdx.x * blockDim.x + threadIdx.x;
    int i4 = i * 4;
    if (i4 + 3 < n) {
        *reinterpret_cast<float4*>(out + i4) = make_float4(0.f, 0.f, 0.f, 0.f);
    } else {
        for (int k = i4; k < n; ++k) out[k] = 0.0f;
    }
}

__device__ __forceinline__ float half_edge_energy(float x, float y, float z) {
    float r2 = fmaf(x, x, fmaf(y, y, z * z));
    float inv = __fdividef(1.0f, r2);      // MUFU.RCP
    float sr6 = inv * inv * inv;           // (sigma/r)^6, sigma=1
    float d = fmaf(sr6, sr6, -sr6);        // sr12 - sr6
    return fmaf(2.0f, d, NEG_HALF_SHIFT);  // 2*(sr12-sr6) - SHIFT/2
}

// 8 edges per thread: front-batched vector loads (MLP ~10), then 16 REDGs.
__global__ __launch_bounds__(256) void lj_scatter_kernel(
    const float* __restrict__ dist,   // [E,3] float32
    const int* __restrict__ ia,       // [E] int32
    const int* __restrict__ ib,       // [E] int32
    float* __restrict__ out,          // [n_atoms]
    int n_edges)
{
    int g = blockIdx.x * blockDim.x + threadIdx.x;
    int base = g * 8;
    if (base >= n_edges) return;

    if (base + 7 < n_edges) {
        // 8 edges = 24 floats = 6x float4 (offset 96B*g -> 16B aligned)
        const float4* d4 = reinterpret_cast<const float4*>(dist + (size_t)base * 3);
        float4 p0 = d4[0];
        float4 p1 = d4[1];
        float4 p2 = d4[2];
        float4 p3 = d4[3];
        float4 p4 = d4[4];
        float4 p5 = d4[5];
        // indices: 2x int4 each (base % 8 == 0 -> 16B aligned)
        const int4* a4 = reinterpret_cast<const int4*>(ia + base);
        const int4* b4 = reinterpret_cast<const int4*>(ib + base);
        int4 a0 = a4[0], a1 = a4[1];
        int4 b0 = b4[0], b1 = b4[1];

        float h0 = half_edge_energy(p0.x, p0.y, p0.z);
        float h1 = half_edge_energy(p0.w, p1.x, p1.y);
        float h2 = half_edge_energy(p1.z, p1.w, p2.x);
        float h3 = half_edge_energy(p2.y, p2.z, p2.w);
        float h4 = half_edge_energy(p3.x, p3.y, p3.z);
        float h5 = half_edge_energy(p3.w, p4.x, p4.y);
        float h6 = half_edge_energy(p4.z, p4.w, p5.x);
        float h7 = half_edge_energy(p5.y, p5.z, p5.w);

        // Return values discarded -> REDG (no-return atomics)
        atomicAdd(out + a0.x, h0);
        atomicAdd(out + b0.x, h0);
        atomicAdd(out + a0.y, h1);
        atomicAdd(out + b0.y, h1);
        atomicAdd(out + a0.z, h2);
        atomicAdd(out + b0.z, h2);
        atomicAdd(out + a0.w, h3);
        atomicAdd(out + b0.w, h3);
        atomicAdd(out + a1.x, h4);
        atomicAdd(out + b1.x, h4);
        atomicAdd(out + a1.y, h5);
        atomicAdd(out + b1.y, h5);
        atomicAdd(out + a1.z, h6);
        atomicAdd(out + b1.z, h6);
        atomicAdd(out + a1.w, h7);
        atomicAdd(out + b1.w, h7);
    } else {
        // Scalar tail
        for (int e = base; e < n_edges; ++e) {
            float x = dist[(size_t)e * 3 + 0];
            float y = dist[(size_t)e * 3 + 1];
            float z = dist[(size_t)e * 3 + 2];
            float h = half_edge_energy(x, y, z);
            atomicAdd(out + ia[e], h);
            atomicAdd(out + ib[e], h);
        }
    }
}

extern "C" void kernel_launch(void* const* d_in, const int* in_sizes, int n_in,
                              void* d_out, int out_size) {
    const float* dist = (const float*)d_in[0]; // [E,3] float32
    const int* ia = (const int*)d_in[1];       // [E] int32
    const int* ib = (const int*)d_in[2];       // [E] int32
    float* out = (float*)d_out;                // [n_atoms] float32

    int n_edges = in_sizes[1];
    int n_atoms = out_size;

    // Zero output (poisoned to 0xAA by harness). float4-vectorized.
    {
        int tpb = 256;
        int groups = (n_atoms + 3) / 4;
        int blocks = (groups + tpb - 1) / tpb;
        zero_out_kernel<<<blocks, tpb>>>(out, n_atoms);
    }

    {
        int tpb = 256;
        int groups = (n_edges + 7) / 8;
        int blocks = (groups + tpb - 1) / tpb;
        lj_scatter_kernel<<<blocks, tpb>>>(dist, ia, ib, out, n_edges);
    }
}